// round 17
// baseline (speedup 1.0000x reference)
#include <cuda_runtime.h>
#include <cuda_fp16.h>

#define DM   1024
#define HEADS 16
#define DH    64
#define POS  2048
#define BATCH 2
#define TOK  (BATCH*POS)   // 4096

// ---------------- scratch (device globals: allocation-free) ----------------
__device__ __half g_Xf[TOK*DM];
__device__ __half g_Qf[TOK*DM], g_Kf[TOK*DM], g_Vf[TOK*DM];
__device__ __half g_Af[TOK*DM];
__device__ __half g_Wqf[DM*DM], g_Wkf[DM*DM], g_Wvf[DM*DM], g_Wof[DM*DM];

// Q pre-scale: 1/sqrt(64) * log2(e)  -> attention scores land in log2 domain
#define QSCALE 0.180336879f

// ---------------- helpers ----------------
__device__ __forceinline__ unsigned smem_u32(const void* p) {
    unsigned r;
    asm("{ .reg .u64 t; cvta.to.shared.u64 t, %1; cvt.u32.u64 %0, t; }" : "=r"(r) : "l"(p));
    return r;
}
__device__ __forceinline__ void cp16(unsigned s, const void* g) {
    asm volatile("cp.async.cg.shared.global [%0], [%1], 16;" :: "r"(s), "l"(g) : "memory");
}
#define CP_ASYNC_COMMIT() asm volatile("cp.async.commit_group;" ::: "memory")
#define CP_ASYNC_WAIT1()  asm volatile("cp.async.wait_group 1;" ::: "memory")
#define CP_ASYNC_WAIT0()  asm volatile("cp.async.wait_group 0;" ::: "memory")

__device__ __forceinline__ void ldsm4(unsigned* r, unsigned a) {
    asm volatile("ldmatrix.sync.aligned.m8n8.x4.shared.b16 {%0,%1,%2,%3}, [%4];"
        : "=r"(r[0]), "=r"(r[1]), "=r"(r[2]), "=r"(r[3]) : "r"(a));
}
__device__ __forceinline__ void ldsm2(unsigned* r, unsigned a) {
    asm volatile("ldmatrix.sync.aligned.m8n8.x2.shared.b16 {%0,%1}, [%2];"
        : "=r"(r[0]), "=r"(r[1]) : "r"(a));
}
__device__ __forceinline__ void ldsm2t(unsigned* r, unsigned a) {
    asm volatile("ldmatrix.sync.aligned.m8n8.x2.trans.shared.b16 {%0,%1}, [%2];"
        : "=r"(r[0]), "=r"(r[1]) : "r"(a));
}
__device__ __forceinline__ void ldsm4t(unsigned* r, unsigned a) {
    asm volatile("ldmatrix.sync.aligned.m8n8.x4.trans.shared.b16 {%0,%1,%2,%3}, [%4];"
        : "=r"(r[0]), "=r"(r[1]), "=r"(r[2]), "=r"(r[3]) : "r"(a));
}
__device__ __forceinline__ void mma_f16(float* d, const unsigned* a, const unsigned* b) {
    asm volatile("mma.sync.aligned.m16n8k16.row.col.f32.f16.f16.f32 "
        "{%0,%1,%2,%3}, {%4,%5,%6,%7}, {%8,%9}, {%0,%1,%2,%3};"
        : "+f"(d[0]), "+f"(d[1]), "+f"(d[2]), "+f"(d[3])
        : "r"(a[0]), "r"(a[1]), "r"(a[2]), "r"(a[3]), "r"(b[0]), "r"(b[1]));
}
// pack two floats to half2, then 2^x on both halves in one MUFU op
__device__ __forceinline__ unsigned h2ex2(float a, float b) {
    __half2 t = __floats2half2_rn(a, b);
    unsigned u = *(unsigned*)&t;
    asm("ex2.approx.f16x2 %0, %0;" : "+r"(u));
    return u;
}
__device__ __forceinline__ float ex2f(float x) {
    float r; asm("ex2.approx.f32 %0, %1;" : "=f"(r) : "f"(x)); return r;
}

// ---------------- fused fp32 -> fp16 conversions (one launch) ----------------
// grid (32, 32, 8), block 1024.
// z<4: weight transpose+convert -> Wt[n][k] fp16.
//   z<3 (QKV layout): src (k,n) = W[n>>6][k][n&63].  z=3 (out): src (k,n) = W[k*DM+n].
// z>=4: straight convert of X quadrant (z-4): rows [(z-4)*1024, ...+1024).
__global__ __launch_bounds__(1024)
void cvt_all(const float* __restrict__ X,
             const float* __restrict__ Wq, const float* __restrict__ Wk,
             const float* __restrict__ Wv, const float* __restrict__ Wo,
             __half* __restrict__ Xf,
             __half* __restrict__ Fq, __half* __restrict__ Fk,
             __half* __restrict__ Fv, __half* __restrict__ Fo)
{
    int z = blockIdx.z;
    int tx = threadIdx.x & 31, ty = threadIdx.x >> 5;
    if (z >= 4) {
        int row = (z - 4) * 1024 + blockIdx.y * 32 + ty;
        int col = blockIdx.x * 32 + tx;
        size_t o = (size_t)row * DM + col;
        Xf[o] = __float2half(X[o]);
        return;
    }
    __shared__ float tile[32][33];
    const float* W = (z == 0) ? Wq : (z == 1) ? Wk : (z == 2) ? Wv : Wo;
    __half* f = (z == 0) ? Fq : (z == 1) ? Fk : (z == 2) ? Fv : Fo;
    int n0 = blockIdx.x * 32, k0 = blockIdx.y * 32;
    {
        int n = n0 + tx, k = k0 + ty;
        float x = (z < 3) ? W[(size_t)(n >> 6) * (DM * DH) + (size_t)k * DH + (n & 63)]
                          : W[(size_t)k * DM + n];
        tile[ty][tx] = x;
    }
    __syncthreads();
    {
        int n = n0 + ty, k = k0 + tx;
        f[(size_t)n * DM + k] = __float2half(tile[tx][ty]);
    }
}

// ---------------- fp16 HMMA GEMM: O[4096x1024] = A x B^T ----------------
// MODE 0: epilogue fp16 (Q/K/V; z==0 output pre-scaled by QSCALE). MODE 1: fp32.
#define TILE_B   18432      // 128 rows x 144B
#define STAGE_B  36864
#define NCHUNK   16
#define GEMM_SMEM_BYTES (2*STAGE_B)  // 73728

template<int MODE>
__global__ __launch_bounds__(256, 2)
void mma_gemm(const __half* __restrict__ A,
              const __half* __restrict__ B0, const __half* __restrict__ B1,
              const __half* __restrict__ B2,
              float* __restrict__ Of,
              __half* O0, __half* O1, __half* O2)
{
    extern __shared__ __align__(128) char smem[];
    const unsigned sb = smem_u32(smem);
    int tid = threadIdx.x, lane = tid & 31, wid = tid >> 5;
    int n0 = blockIdx.x * 128, m0 = blockIdx.y * 128;
    int z = blockIdx.z;
    const char* pA = (const char*)A;
    const char* pB = (const char*)((z == 0) ? B0 : (z == 1) ? B1 : B2);
    __half* Oh = (z == 0) ? O0 : (z == 1) ? O1 : O2;

    int wm = (wid & 1) * 64;
    int wn = (wid >> 1) * 32;
    int lr = tid >> 3;
    int lc = (tid & 7) * 16;

    float acc[4][4][4];
#pragma unroll
    for (int mi = 0; mi < 4; mi++)
#pragma unroll
        for (int ni = 0; ni < 4; ni++)
#pragma unroll
            for (int e = 0; e < 4; e++) acc[mi][ni][e] = 0.0f;

    auto load_chunk = [&](int c, int st) {
        int k0b = c * 128;
#pragma unroll
        for (int q = 0; q < 4; q++) {
            int row = lr + q * 32;
            unsigned sa = sb + st * STAGE_B + row * 144 + lc;
            size_t goffA = ((size_t)(m0 + row) * DM) * 2 + k0b + lc;
            size_t goffB = ((size_t)(n0 + row) * DM) * 2 + k0b + lc;
            cp16(sa,          pA + goffA);
            cp16(sa + TILE_B, pB + goffB);
        }
    };

    load_chunk(0, 0);
    CP_ASYNC_COMMIT();

    unsigned a_base = (wm + (lane & 15)) * 144 + ((lane >> 4) << 4);
    unsigned b_base = TILE_B + (wn + (lane & 7)) * 144 + (((lane >> 3) & 1) << 4);

    for (int c = 0; c < NCHUNK; c++) {
        if (c + 1 < NCHUNK) {
            load_chunk(c + 1, (c + 1) & 1);
            CP_ASYNC_COMMIT();
            CP_ASYNC_WAIT1();
        } else {
            CP_ASYNC_WAIT0();
        }
        __syncthreads();

        unsigned stb = sb + (c & 1) * STAGE_B;
#pragma unroll
        for (int ks = 0; ks < 4; ks++) {
            unsigned af[4][4], bf[4][2];
            unsigned ka = stb + ks * 32;
#pragma unroll
            for (int mi = 0; mi < 4; mi++) ldsm4(af[mi], ka + a_base + mi * (16 * 144));
#pragma unroll
            for (int ni = 0; ni < 4; ni++) ldsm2(bf[ni], ka + b_base + ni * (8 * 144));
#pragma unroll
            for (int mi = 0; mi < 4; mi++)
#pragma unroll
                for (int ni = 0; ni < 4; ni++) mma_f16(acc[mi][ni], af[mi], bf[ni]);
        }
        __syncthreads();
    }

    int g = lane >> 2, t = lane & 3;
    float sc = (MODE == 0 && z == 0) ? QSCALE : 1.0f;
#pragma unroll
    for (int mi = 0; mi < 4; mi++) {
#pragma unroll
        for (int ni = 0; ni < 4; ni++) {
            int row = m0 + wm + mi * 16 + g;
            int col = n0 + wn + ni * 8 + t * 2;
            if (MODE == 1) {
                float2 v0 = { acc[mi][ni][0], acc[mi][ni][1] };
                float2 v1 = { acc[mi][ni][2], acc[mi][ni][3] };
                *(float2*)(Of + (size_t)row * DM + col)       = v0;
                *(float2*)(Of + (size_t)(row + 8) * DM + col) = v1;
            } else {
                *(__half2*)(Oh + (size_t)row * DM + col) =
                    __floats2half2_rn(acc[mi][ni][0] * sc, acc[mi][ni][1] * sc);
                *(__half2*)(Oh + (size_t)(row + 8) * DM + col) =
                    __floats2half2_rn(acc[mi][ni][2] * sc, acc[mi][ni][3] * sc);
            }
        }
    }
}

// ---------------- HMMA flash attention (causal, fp16, log2-domain softmax) ----------------
// CTA: 128 queries x (b,h). 8 warps, warp = 16 query rows.
// KV staged 128 keys at a time (two 64-key sub-blocks between one barrier pair).
// Q pre-scaled by 0.125*log2e -> S is log2-domain; P = ex2.f16x2(S - m).
// l accumulated by an extra HMMA against a constant ones-column in the V row pad.
#define AQ   128
#define AKB  128                 // keys per stage
#define QST  144
#define KST  144
#define Q_TILE   (AQ*QST)        // 18432
#define KV_TILE  (AKB*KST)       // 18432 (K tile; V tile same)
#define KV_STAGE (2*KV_TILE)     // 36864  (K + V)
#define ATTN_SMEM (Q_TILE + 2*KV_STAGE)  // 92160

__global__ __launch_bounds__(256, 2)
void attn_mma()
{
    extern __shared__ __align__(128) char smem[];
    const unsigned sb = smem_u32(smem);
    int tid = threadIdx.x, lane = tid & 31, w = tid >> 5;
    int g = lane >> 2, t = lane & 3;
    int qt = (int)gridDim.x - 1 - (int)blockIdx.x;   // big tiles first
    int h = blockIdx.y, b = blockIdx.z;
    int q0 = qt * AQ;
    const char* pQf = (const char*)g_Qf;
    const char* pKf = (const char*)g_Kf;
    const char* pVf = (const char*)g_Vf;

    // ones-column pattern in the V row pad (bytes 128..143 of each V row, both stages)
    {
        int st = tid >> 7, row = tid & 127;
        *(uint4*)(smem + Q_TILE + st * KV_STAGE + KV_TILE + row * KST + 128) =
            make_uint4(0x00003C00u, 0u, 0u, 0u);   // fp16 1.0 at pad col 0, zeros elsewhere
    }

    // stage Q tile (128 rows x 128B)
#pragma unroll
    for (int i = 0; i < 4; i++) {
        int idx = tid + 256 * i;
        int row = idx >> 3, c16 = idx & 7;
        size_t off = ((size_t)(b * POS + q0 + row) * DM + h * DH) * 2 + c16 * 16;
        cp16(sb + row * QST + c16 * 16, pQf + off);
    }

    auto load_kv = [&](int kb, int st) {
        int k0 = kb * AKB;
        unsigned base = sb + Q_TILE + st * KV_STAGE;
#pragma unroll
        for (int i = 0; i < 4; i++) {
            int idx = tid + 256 * i;      // 0..1023: 128 rows x 8 16B-cols
            int row = idx >> 3, c16 = idx & 7;
            size_t off = ((size_t)(b * POS + k0 + row) * DM + h * DH) * 2 + c16 * 16;
            unsigned d = base + row * KST + c16 * 16;
            cp16(d,           pKf + off);
            cp16(d + KV_TILE, pVf + off);
        }
    };

    load_kv(0, 0);
    CP_ASYNC_COMMIT();

    int nkb = qt + 1;                 // 128-key blocks
    int qr0 = q0 + 16 * w + g;
    float m0 = -1e30f, m1 = -1e30f;
    float o[8][4];
    float oc[4] = {0.0f, 0.0f, 0.0f, 0.0f};   // ones-column accumulator (l at t=0)
#pragma unroll
    for (int ni = 0; ni < 8; ni++)
#pragma unroll
        for (int e = 0; e < 4; e++) o[ni][e] = 0.0f;

    unsigned qf[4][4];
    unsigned bones[2];
    unsigned qa = sb + (16 * w + (lane & 15)) * QST + ((lane >> 4) << 4);

    for (int kb = 0; kb < nkb; kb++) {
        if (kb + 1 < nkb) {
            load_kv(kb + 1, (kb + 1) & 1);
            CP_ASYNC_COMMIT();
            CP_ASYNC_WAIT1();
        } else {
            CP_ASYNC_WAIT0();
        }
        __syncthreads();
        if (kb == 0) {
#pragma unroll
            for (int ks = 0; ks < 4; ks++) ldsm4(qf[ks], qa + ks * 32);
            // constant ones-column B fragment (same everywhere) - load once
            ldsm2t(bones, sb + Q_TILE + KV_TILE + (lane & 15) * KST + 128);
        }

        unsigned stg = sb + Q_TILE + (kb & 1) * KV_STAGE;
#pragma unroll
        for (int sub = 0; sub < 2; sub++) {
            int k0s = kb * AKB + sub * 64;
            unsigned sbo = stg + sub * (64 * KST);
            if (k0s > q0 + 16 * w + 15) continue;   // fully masked for this warp

            // ---- S = Qf * Kf^T (log2 domain; scale pre-folded into Q) ----
            float s[8][4];
#pragma unroll
            for (int ni = 0; ni < 8; ni++)
#pragma unroll
                for (int e = 0; e < 4; e++) s[ni][e] = 0.0f;
            unsigned kb4 = sbo + ((lane & 7) + ((lane >> 4) << 3)) * KST + (((lane >> 3) & 1) << 4);
#pragma unroll
            for (int ks = 0; ks < 4; ks++)
#pragma unroll
                for (int nip = 0; nip < 4; nip++) {
                    unsigned bf4[4];
                    ldsm4(bf4, kb4 + nip * (16 * KST) + ks * 32);
                    mma_f16(s[2*nip],   qf[ks], bf4);
                    mma_f16(s[2*nip+1], qf[ks], bf4 + 2);
                }
            // ---- causal mask ----
            if (k0s + 63 > qr0) {
#pragma unroll
                for (int ni = 0; ni < 8; ni++) {
                    int kc = k0s + ni * 8 + t * 2;
                    if (kc     > qr0)     s[ni][0] = -1e30f;
                    if (kc + 1 > qr0)     s[ni][1] = -1e30f;
                    if (kc     > qr0 + 8) s[ni][2] = -1e30f;
                    if (kc + 1 > qr0 + 8) s[ni][3] = -1e30f;
                }
            }
            // ---- online max (warp-local, rows g and g+8) ----
            float bm0 = -1e30f, bm1 = -1e30f;
#pragma unroll
            for (int ni = 0; ni < 8; ni++) {
                bm0 = fmaxf(bm0, fmaxf(s[ni][0], s[ni][1]));
                bm1 = fmaxf(bm1, fmaxf(s[ni][2], s[ni][3]));
            }
            bm0 = fmaxf(bm0, __shfl_xor_sync(0xffffffffu, bm0, 1));
            bm0 = fmaxf(bm0, __shfl_xor_sync(0xffffffffu, bm0, 2));
            bm1 = fmaxf(bm1, __shfl_xor_sync(0xffffffffu, bm1, 1));
            bm1 = fmaxf(bm1, __shfl_xor_sync(0xffffffffu, bm1, 2));
            float mn0 = fmaxf(m0, bm0), mn1 = fmaxf(m1, bm1);
            float a0 = ex2f(m0 - mn0), a1 = ex2f(m1 - mn1);
            m0 = mn0; m1 = mn1;
#pragma unroll
            for (int ni = 0; ni < 8; ni++) {
                o[ni][0] *= a0; o[ni][1] *= a0;
                o[ni][2] *= a1; o[ni][3] *= a1;
            }
            oc[0] *= a0; oc[1] *= a0; oc[2] *= a1; oc[3] *= a1;
            // ---- O += P * V;  P = ex2.f16x2(S - m) built in-loop ----
            unsigned vb4 = sbo + KV_TILE + (lane & 15) * KST + ((lane >> 4) << 4);
#pragma unroll
            for (int ks = 0; ks < 4; ks++) {
                int i0 = 2 * ks, i1 = 2 * ks + 1;
                unsigned aP[4] = {
                    h2ex2(s[i0][0] - m0, s[i0][1] - m0),
                    h2ex2(s[i0][2] - m1, s[i0][3] - m1),
                    h2ex2(s[i1][0] - m0, s[i1][1] - m0),
                    h2ex2(s[i1][2] - m1, s[i1][3] - m1)
                };
#pragma unroll
                for (int nip = 0; nip < 4; nip++) {
                    unsigned bv[4];
                    ldsm4t(bv, vb4 + ks * (16 * KST) + nip * 32);
                    mma_f16(o[2*nip],   aP, bv);
                    mma_f16(o[2*nip+1], aP, bv + 2);
                }
                mma_f16(oc, aP, bones);   // l accumulation via ones column
            }
        }
        __syncthreads();
    }

    // ---- finalize: l from ones-column (t=0 lane of each quad), O/l, fp16 out ----
    float l0 = __shfl_sync(0xffffffffu, oc[0], lane & 28);
    float l1 = __shfl_sync(0xffffffffu, oc[2], lane & 28);
    float inv0 = 1.0f / l0, inv1 = 1.0f / l1;
    size_t r0off = (size_t)(b * POS + qr0) * DM + h * DH;
    size_t r1off = r0off + (size_t)8 * DM;
#pragma unroll
    for (int ni = 0; ni < 8; ni++) {
        int col = ni * 8 + t * 2;
        *(__half2*)(g_Af + r0off + col) = __floats2half2_rn(o[ni][0] * inv0, o[ni][1] * inv0);
        *(__half2*)(g_Af + r1off + col) = __floats2half2_rn(o[ni][2] * inv1, o[ni][3] * inv1);
    }
}

// ---------------- launch ----------------
extern "C" void kernel_launch(void* const* d_in, const int* in_sizes, int n_in,
                              void* d_out, int out_size)
{
    (void)in_sizes; (void)n_in; (void)out_size;
    const float* X  = (const float*)d_in[0];
    const float* Wq = (const float*)d_in[1];
    const float* Wk = (const float*)d_in[2];
    const float* Wv = (const float*)d_in[3];
    const float* Wo = (const float*)d_in[4];
    float* out = (float*)d_out;

    __half *Xf, *Qf, *Kf, *Vf, *Af, *Wqf, *Wkf, *Wvf, *Wof;
    cudaGetSymbolAddress((void**)&Xf,  g_Xf);
    cudaGetSymbolAddress((void**)&Qf,  g_Qf);
    cudaGetSymbolAddress((void**)&Kf,  g_Kf);
    cudaGetSymbolAddress((void**)&Vf,  g_Vf);
    cudaGetSymbolAddress((void**)&Af,  g_Af);
    cudaGetSymbolAddress((void**)&Wqf, g_Wqf);
    cudaGetSymbolAddress((void**)&Wkf, g_Wkf);
    cudaGetSymbolAddress((void**)&Wvf, g_Wvf);
    cudaGetSymbolAddress((void**)&Wof, g_Wof);

    cudaFuncSetAttribute(mma_gemm<0>, cudaFuncAttributeMaxDynamicSharedMemorySize, GEMM_SMEM_BYTES);
    cudaFuncSetAttribute(mma_gemm<1>, cudaFuncAttributeMaxDynamicSharedMemorySize, GEMM_SMEM_BYTES);
    cudaFuncSetAttribute(attn_mma,    cudaFuncAttributeMaxDynamicSharedMemorySize, ATTN_SMEM);

    // 0) all fp32->fp16 conversions in one launch
    dim3 gc(DM / 32, DM / 32, 8);
    cvt_all<<<gc, 1024>>>(X, Wq, Wk, Wv, Wo, Xf, Wqf, Wkf, Wvf, Wof);

    // 1) fused QKV projection (fp16) -> fp16 Q (pre-scaled), K, V
    dim3 g1(DM / 128, TOK / 128, 3);
    mma_gemm<0><<<g1, 256, GEMM_SMEM_BYTES>>>(Xf, Wqf, Wkf, Wvf, nullptr, Qf, Kf, Vf);

    // 2) causal flash attention (fp16, log2-domain softmax, 128-key stages) -> fp16 A
    dim3 g2(POS / AQ, HEADS, BATCH);
    attn_mma<<<g2, 256, ATTN_SMEM>>>();

    // 3) out projection (fp16) -> fp32 output
    dim3 g3(DM / 128, TOK / 128, 1);
    mma_gemm<1><<<g3, 256, GEMM_SMEM_BYTES>>>(Af, Wof, nullptr, nullptr, out, nullptr, nullptr, nullptr);
}